// round 1
// baseline (speedup 1.0000x reference)
#include <cuda_runtime.h>
#include <cuda_bf16.h>
#include <math.h>

// Problem constants (fixed by the reference setup)
#define NMAX 100000
#define DMAX 64
#define HEADS 4
#define EMAX 3200000
#define EPS 1e-15f
#define ALPHA 0.2f       // leaky slope inside attention
#define ACT_SLOPE 0.01f  // final leaky slope
#define MAXNORM 0.996f   // (1 - 4e-3)/sqrt(c), c=1

// ---------------- device scratch (static; no runtime allocation) -------------
__device__ float g_xtan[NMAX * DMAX];            // 25.6 MB
__device__ float g_h[HEADS][NMAX * DMAX];        // 102.4 MB
__device__ float g_ssrc[HEADS][NMAX];
__device__ float g_sdst[HEADS][NMAX];
__device__ int   g_deg[NMAX];
__device__ int   g_rowptr[NMAX + 1];
__device__ int   g_cursor[NMAX];
__device__ int   g_dsts[EMAX];                   // dst sorted by src (CSR payload)
__device__ int   g_bsum[1024];

// ---------------- K1: logmap0 ------------------------------------------------
// warp per node: x_tan = artanh(clip(||x||)) * x / max(||x||, eps)
__global__ void k_logmap(const float* __restrict__ x, int n) {
    int wid  = (blockIdx.x * blockDim.x + threadIdx.x) >> 5;
    int lane = threadIdx.x & 31;
    if (wid >= n) return;
    float2 v = *reinterpret_cast<const float2*>(x + (size_t)wid * DMAX + lane * 2);
    float ss = v.x * v.x + v.y * v.y;
    #pragma unroll
    for (int o = 16; o > 0; o >>= 1) ss += __shfl_xor_sync(0xffffffffu, ss, o);
    float nrm = fmaxf(sqrtf(ss), EPS);
    float cl  = fminf(nrm, 1.0f - 1e-7f);
    float at  = 0.5f * (log1pf(cl) - log1pf(-cl));   // artanh
    float f   = at / nrm;
    float2 o2 = make_float2(v.x * f, v.y * f);
    *reinterpret_cast<float2*>(g_xtan + (size_t)wid * DMAX + lane * 2) = o2;
}

// ---------------- K2: per-head GEMM h = x_tan @ W[hd], + score projections ---
// 64-row tile per block, 256 threads (16x16), 4x4 outputs per thread.
// Epilogue computes s_src = h . a[:64], s_dst = h . a[64:] via half-warp shfl.
__global__ __launch_bounds__(256) void k_gemm(const float* __restrict__ W,
                                              const float* __restrict__ a,
                                              int n) {
    const int hd   = blockIdx.y;
    const int row0 = blockIdx.x * 64;
    __shared__ float Ws[64 * 64];
    __shared__ float Xs[64 * 64];
    __shared__ float As[128];
    const int tid = threadIdx.x;
    // load W[hd] (k-major: W[hd][k][c])
    for (int i = tid; i < 4096; i += 256) Ws[i] = W[hd * 4096 + i];
    for (int i = tid; i < 4096; i += 256) {
        int r = row0 + (i >> 6);
        Xs[i] = (r < n) ? g_xtan[(size_t)r * DMAX + (i & 63)] : 0.0f;
    }
    if (tid < 128) As[tid] = a[hd * 128 + tid];
    __syncthreads();

    const int ty = tid >> 4;   // 0..15 (row group)
    const int tx = tid & 15;   // 0..15 (col group)
    float acc[4][4];
    #pragma unroll
    for (int i = 0; i < 4; i++)
        #pragma unroll
        for (int j = 0; j < 4; j++) acc[i][j] = 0.0f;

    #pragma unroll 8
    for (int k = 0; k < 64; k++) {
        float4 wv = *reinterpret_cast<const float4*>(&Ws[k * 64 + tx * 4]);
        #pragma unroll
        for (int i = 0; i < 4; i++) {
            float xv = Xs[(ty * 4 + i) * 64 + k];
            acc[i][0] = fmaf(xv, wv.x, acc[i][0]);
            acc[i][1] = fmaf(xv, wv.y, acc[i][1]);
            acc[i][2] = fmaf(xv, wv.z, acc[i][2]);
            acc[i][3] = fmaf(xv, wv.w, acc[i][3]);
        }
    }

    float al0 = As[tx * 4 + 0], al1 = As[tx * 4 + 1], al2 = As[tx * 4 + 2], al3 = As[tx * 4 + 3];
    float ar0 = As[64 + tx * 4 + 0], ar1 = As[64 + tx * 4 + 1], ar2 = As[64 + tx * 4 + 2], ar3 = As[64 + tx * 4 + 3];
    #pragma unroll
    for (int i = 0; i < 4; i++) {
        int r = row0 + ty * 4 + i;
        if (r < n) {
            float4 hv = make_float4(acc[i][0], acc[i][1], acc[i][2], acc[i][3]);
            *reinterpret_cast<float4*>(&g_h[hd][(size_t)r * DMAX + tx * 4]) = hv;
        }
        float pl = acc[i][0]*al0 + acc[i][1]*al1 + acc[i][2]*al2 + acc[i][3]*al3;
        float pr = acc[i][0]*ar0 + acc[i][1]*ar1 + acc[i][2]*ar2 + acc[i][3]*ar3;
        #pragma unroll
        for (int o = 8; o > 0; o >>= 1) {
            pl += __shfl_xor_sync(0xffffffffu, pl, o);
            pr += __shfl_xor_sync(0xffffffffu, pr, o);
        }
        if (tx == 0 && r < n) { g_ssrc[hd][r] = pl; g_sdst[hd][r] = pr; }
    }
}

// ---------------- K3: CSR construction ---------------------------------------
__global__ void k_zero(int n) {
    int i = blockIdx.x * blockDim.x + threadIdx.x;
    if (i < n) g_deg[i] = 0;
}
__global__ void k_count(const int* __restrict__ src, int e) {
    int i = blockIdx.x * blockDim.x + threadIdx.x;
    if (i < e) atomicAdd(&g_deg[src[i]], 1);
}
// exclusive scan over deg -> rowptr (1024-chunk, 3-pass)
__global__ __launch_bounds__(1024) void k_scan1(int n) {
    __shared__ int s[1024];
    int t = threadIdx.x;
    int i = blockIdx.x * 1024 + t;
    int v = (i < n) ? g_deg[i] : 0;
    s[t] = v;
    #pragma unroll
    for (int off = 1; off < 1024; off <<= 1) {
        __syncthreads();
        int add = (t >= off) ? s[t - off] : 0;
        __syncthreads();
        s[t] += add;
    }
    __syncthreads();
    if (i < n) g_rowptr[i] = s[t] - v;      // exclusive within block
    if (t == 1023) g_bsum[blockIdx.x] = s[1023];
}
__global__ void k_scan2(int n, int nblk) {
    if (threadIdx.x == 0 && blockIdx.x == 0) {
        int run = 0;
        for (int b = 0; b < nblk; b++) { int t = g_bsum[b]; g_bsum[b] = run; run += t; }
        g_rowptr[n] = run;
    }
}
__global__ __launch_bounds__(1024) void k_scan3(int n) {
    int i = blockIdx.x * 1024 + threadIdx.x;
    if (i < n) {
        int v = g_rowptr[i] + g_bsum[blockIdx.x];
        g_rowptr[i] = v;
        g_cursor[i] = v;
    }
}
__global__ void k_scatter(const int* __restrict__ src, const int* __restrict__ dst, int e) {
    int i = blockIdx.x * blockDim.x + threadIdx.x;
    if (i < e) {
        int p = atomicAdd(&g_cursor[src[i]], 1);
        g_dsts[p] = dst[i];
    }
}

// ---------------- K4: per-head aggregation (warp per node) -------------------
// num[n] = sum_e w_e * h[dst_e];  denom[n] = sum_e w_e
// w_e = exp(-leaky_relu(s_src[n] + s_dst[dst_e], 0.2))
__global__ __launch_bounds__(256) void k_agg(int n, int hd, float* __restrict__ out) {
    int wid  = (blockIdx.x * blockDim.x + threadIdx.x) >> 5;
    int lane = threadIdx.x & 31;
    if (wid >= n) return;
    int beg = g_rowptr[wid];
    int end = g_rowptr[wid + 1];
    const float ssn = g_ssrc[hd][wid];
    const float* __restrict__ hb = g_h[hd];
    const float* __restrict__ sd = g_sdst[hd];
    float ax = 0.0f, ay = 0.0f, den = 0.0f;
    for (int e = beg; e < end; e++) {
        int d = __ldg(&g_dsts[e]);
        float s  = ssn + __ldg(&sd[d]);
        float sl = (s > 0.0f) ? s : ALPHA * s;
        float w  = __expf(-sl);
        float2 hv = *reinterpret_cast<const float2*>(hb + (size_t)d * DMAX + lane * 2);
        ax = fmaf(w, hv.x, ax);
        ay = fmaf(w, hv.y, ay);
        den += w;
    }
    float inv = 1.0f / (den + EPS);
    ax *= inv; ay *= inv;
    ax = (ax > 0.0f) ? ax : ACT_SLOPE * ax;
    ay = (ay > 0.0f) ? ay : ACT_SLOPE * ay;
    *reinterpret_cast<float2*>(out + (size_t)wid * 256 + hd * 64 + lane * 2) =
        make_float2(ax, ay);
}

// ---------------- K5: expmap0 + proj, in place on out [N,256] ----------------
__global__ void k_final(float* __restrict__ out, int n) {
    int wid  = (blockIdx.x * blockDim.x + threadIdx.x) >> 5;
    int lane = threadIdx.x & 31;
    if (wid >= n) return;
    float* row = out + (size_t)wid * 256;
    float4 v0 = *reinterpret_cast<float4*>(row + lane * 8);
    float4 v1 = *reinterpret_cast<float4*>(row + lane * 8 + 4);
    float ss = v0.x*v0.x + v0.y*v0.y + v0.z*v0.z + v0.w*v0.w
             + v1.x*v1.x + v1.y*v1.y + v1.z*v1.z + v1.w*v1.w;
    #pragma unroll
    for (int o = 16; o > 0; o >>= 1) ss += __shfl_xor_sync(0xffffffffu, ss, o);
    float nrm = sqrtf(ss);
    float un  = fmaxf(nrm, EPS);
    float th  = tanhf(un);
    float f   = th / un;              // expmap0 scale factor
    float pn  = fmaxf(f * nrm, EPS);  // norm after expmap
    if (pn > MAXNORM) f *= MAXNORM / pn;
    v0.x *= f; v0.y *= f; v0.z *= f; v0.w *= f;
    v1.x *= f; v1.y *= f; v1.z *= f; v1.w *= f;
    *reinterpret_cast<float4*>(row + lane * 8)     = v0;
    *reinterpret_cast<float4*>(row + lane * 8 + 4) = v1;
}

// ---------------- launch ------------------------------------------------------
extern "C" void kernel_launch(void* const* d_in, const int* in_sizes, int n_in,
                              void* d_out, int out_size) {
    const float* x  = (const float*)d_in[0];
    const int*   ei = (const int*)d_in[1];
    const float* W  = (const float*)d_in[2];
    const float* a  = (const float*)d_in[3];
    float* out = (float*)d_out;

    const int n = in_sizes[0] / DMAX;
    const int E = in_sizes[1] / 2;
    const int* src = ei;
    const int* dst = ei + E;

    k_logmap<<<(n + 7) / 8, 256>>>(x, n);

    dim3 g2((n + 63) / 64, HEADS);
    k_gemm<<<g2, 256>>>(W, a, n);

    k_zero<<<(n + 255) / 256, 256>>>(n);
    k_count<<<(E + 255) / 256, 256>>>(src, E);
    int G = (n + 1023) / 1024;
    k_scan1<<<G, 1024>>>(n);
    k_scan2<<<1, 32>>>(n, G);
    k_scan3<<<G, 1024>>>(n);
    k_scatter<<<(E + 255) / 256, 256>>>(src, dst, E);

    // one head at a time -> per-head h table (25.6MB) stays L2-resident
    for (int hd = 0; hd < HEADS; hd++)
        k_agg<<<(n + 7) / 8, 256>>>(n, hd, out);

    k_final<<<(n + 7) / 8, 256>>>(out, n);
}

// round 2
// speedup vs baseline: 1.5202x; 1.5202x over previous
#include <cuda_runtime.h>
#include <cuda_bf16.h>
#include <cuda_fp16.h>
#include <math.h>

// Problem constants (fixed by the reference setup)
#define NMAX 100000
#define DMAX 64
#define HEADS 4
#define EMAX 3200000
#define EPS 1e-15f
#define ALPHA 0.2f       // leaky slope inside attention
#define ACT_SLOPE 0.01f  // final leaky slope
#define MAXNORM 0.996f   // (1 - 4e-3)/sqrt(c), c=1

// ---------------- device scratch (static; no runtime allocation) -------------
__device__ float  g_xtan[NMAX * DMAX];           // 25.6 MB
__device__ __half g_hh[(size_t)NMAX * 256];      // 51.2 MB  h interleaved [node][hd*64+c]
__device__ float  g_ssrc4[NMAX * 4];             // scores interleaved [node][hd]
__device__ float  g_sdst4[NMAX * 4];
__device__ int    g_deg[NMAX];
__device__ int    g_rowptr[NMAX + 1];
__device__ int    g_cursor[NMAX];
__device__ int    g_dsts[EMAX];                  // dst sorted by src (CSR payload)
__device__ int    g_bsum[1024];

// ---------------- K1: logmap0 ------------------------------------------------
__global__ void k_logmap(const float* __restrict__ x, int n) {
    int wid  = (blockIdx.x * blockDim.x + threadIdx.x) >> 5;
    int lane = threadIdx.x & 31;
    if (wid >= n) return;
    float2 v = *reinterpret_cast<const float2*>(x + (size_t)wid * DMAX + lane * 2);
    float ss = v.x * v.x + v.y * v.y;
    #pragma unroll
    for (int o = 16; o > 0; o >>= 1) ss += __shfl_xor_sync(0xffffffffu, ss, o);
    float nrm = fmaxf(sqrtf(ss), EPS);
    float cl  = fminf(nrm, 1.0f - 1e-7f);
    float at  = 0.5f * (log1pf(cl) - log1pf(-cl));   // artanh
    float f   = at / nrm;
    *reinterpret_cast<float2*>(g_xtan + (size_t)wid * DMAX + lane * 2) =
        make_float2(v.x * f, v.y * f);
}

// ---------------- K2: per-head GEMM h = x_tan @ W[hd], + score projections ---
// Writes h in fp16 to the interleaved [node][hd*64+c] layout; scores to [node][hd].
__global__ __launch_bounds__(256) void k_gemm(const float* __restrict__ W,
                                              const float* __restrict__ a,
                                              int n) {
    const int hd   = blockIdx.y;
    const int row0 = blockIdx.x * 64;
    __shared__ float Ws[64 * 64];
    __shared__ float Xs[64 * 64];
    __shared__ float As[128];
    const int tid = threadIdx.x;
    for (int i = tid; i < 4096; i += 256) Ws[i] = W[hd * 4096 + i];
    for (int i = tid; i < 4096; i += 256) {
        int r = row0 + (i >> 6);
        Xs[i] = (r < n) ? g_xtan[(size_t)r * DMAX + (i & 63)] : 0.0f;
    }
    if (tid < 128) As[tid] = a[hd * 128 + tid];
    __syncthreads();

    const int ty = tid >> 4;   // 0..15 (row group)
    const int tx = tid & 15;   // 0..15 (col group)
    float acc[4][4];
    #pragma unroll
    for (int i = 0; i < 4; i++)
        #pragma unroll
        for (int j = 0; j < 4; j++) acc[i][j] = 0.0f;

    #pragma unroll 8
    for (int k = 0; k < 64; k++) {
        float4 wv = *reinterpret_cast<const float4*>(&Ws[k * 64 + tx * 4]);
        #pragma unroll
        for (int i = 0; i < 4; i++) {
            float xv = Xs[(ty * 4 + i) * 64 + k];
            acc[i][0] = fmaf(xv, wv.x, acc[i][0]);
            acc[i][1] = fmaf(xv, wv.y, acc[i][1]);
            acc[i][2] = fmaf(xv, wv.z, acc[i][2]);
            acc[i][3] = fmaf(xv, wv.w, acc[i][3]);
        }
    }

    float al0 = As[tx * 4 + 0], al1 = As[tx * 4 + 1], al2 = As[tx * 4 + 2], al3 = As[tx * 4 + 3];
    float ar0 = As[64 + tx * 4 + 0], ar1 = As[64 + tx * 4 + 1], ar2 = As[64 + tx * 4 + 2], ar3 = As[64 + tx * 4 + 3];
    #pragma unroll
    for (int i = 0; i < 4; i++) {
        int r = row0 + ty * 4 + i;
        if (r < n) {
            size_t off = (size_t)r * 256 + hd * 64 + tx * 4;
            __half2 p0 = __floats2half2_rn(acc[i][0], acc[i][1]);
            __half2 p1 = __floats2half2_rn(acc[i][2], acc[i][3]);
            *reinterpret_cast<__half2*>(&g_hh[off])     = p0;
            *reinterpret_cast<__half2*>(&g_hh[off + 2]) = p1;
        }
        float pl = acc[i][0]*al0 + acc[i][1]*al1 + acc[i][2]*al2 + acc[i][3]*al3;
        float pr = acc[i][0]*ar0 + acc[i][1]*ar1 + acc[i][2]*ar2 + acc[i][3]*ar3;
        #pragma unroll
        for (int o = 8; o > 0; o >>= 1) {
            pl += __shfl_xor_sync(0xffffffffu, pl, o);
            pr += __shfl_xor_sync(0xffffffffu, pr, o);
        }
        if (tx == 0 && r < n) { g_ssrc4[r * 4 + hd] = pl; g_sdst4[r * 4 + hd] = pr; }
    }
}

// ---------------- K3: CSR construction ---------------------------------------
__global__ void k_zero(int n) {
    int i = blockIdx.x * blockDim.x + threadIdx.x;
    if (i < n) g_deg[i] = 0;
}
__global__ void k_count(const int* __restrict__ src, int e) {
    int i = blockIdx.x * blockDim.x + threadIdx.x;
    if (i < e) atomicAdd(&g_deg[src[i]], 1);
}
__global__ __launch_bounds__(1024) void k_scan1(int n) {
    __shared__ int s[1024];
    int t = threadIdx.x;
    int i = blockIdx.x * 1024 + t;
    int v = (i < n) ? g_deg[i] : 0;
    s[t] = v;
    #pragma unroll
    for (int off = 1; off < 1024; off <<= 1) {
        __syncthreads();
        int add = (t >= off) ? s[t - off] : 0;
        __syncthreads();
        s[t] += add;
    }
    __syncthreads();
    if (i < n) g_rowptr[i] = s[t] - v;      // exclusive within block
    if (t == 1023) g_bsum[blockIdx.x] = s[1023];
}
__global__ void k_scan2(int n, int nblk) {
    if (threadIdx.x == 0 && blockIdx.x == 0) {
        int run = 0;
        for (int b = 0; b < nblk; b++) { int t = g_bsum[b]; g_bsum[b] = run; run += t; }
        g_rowptr[n] = run;
    }
}
__global__ __launch_bounds__(1024) void k_scan3(int n) {
    int i = blockIdx.x * 1024 + threadIdx.x;
    if (i < n) {
        int v = g_rowptr[i] + g_bsum[blockIdx.x];
        g_rowptr[i] = v;
        g_cursor[i] = v;
    }
}
__global__ void k_scatter(const int* __restrict__ src, const int* __restrict__ dst, int e) {
    int i = blockIdx.x * blockDim.x + threadIdx.x;
    if (i < e) {
        int p = atomicAdd(&g_cursor[src[i]], 1);
        g_dsts[p] = dst[i];
    }
}

// ---------------- K4: fused aggregation, all heads + expmap0/proj ------------
// Warp per node. Lane L owns output columns [L*8, L*8+8); head = L>>3.
// Per edge: one 16B half-gather per lane (512B/warp, 4 L2 lines), score from
// [node][4] interleaved table. den is identical across the 8 lanes of a head.
__global__ __launch_bounds__(256) void k_agg_all(int n, float* __restrict__ out) {
    int wid  = (blockIdx.x * blockDim.x + threadIdx.x) >> 5;
    int lane = threadIdx.x & 31;
    if (wid >= n) return;
    const int hd  = lane >> 3;
    const int beg = g_rowptr[wid];
    const int end = g_rowptr[wid + 1];
    const float ssn = g_ssrc4[wid * 4 + hd];

    float a0 = 0.f, a1 = 0.f, a2 = 0.f, a3 = 0.f;
    float a4 = 0.f, a5 = 0.f, a6 = 0.f, a7 = 0.f;
    float den = 0.f;

    for (int e = beg; e < end; e++) {
        int d = __ldg(&g_dsts[e]);
        float s  = ssn + __ldg(&g_sdst4[d * 4 + hd]);
        float sl = (s > 0.0f) ? s : ALPHA * s;
        float w  = __expf(-sl);
        uint4 hv = *reinterpret_cast<const uint4*>(&g_hh[(size_t)d * 256 + lane * 8]);
        float2 f0 = __half22float2(*reinterpret_cast<__half2*>(&hv.x));
        float2 f1 = __half22float2(*reinterpret_cast<__half2*>(&hv.y));
        float2 f2 = __half22float2(*reinterpret_cast<__half2*>(&hv.z));
        float2 f3 = __half22float2(*reinterpret_cast<__half2*>(&hv.w));
        a0 = fmaf(w, f0.x, a0); a1 = fmaf(w, f0.y, a1);
        a2 = fmaf(w, f1.x, a2); a3 = fmaf(w, f1.y, a3);
        a4 = fmaf(w, f2.x, a4); a5 = fmaf(w, f2.y, a5);
        a6 = fmaf(w, f3.x, a6); a7 = fmaf(w, f3.y, a7);
        den += w;
    }

    float inv = 1.0f / (den + EPS);
    float v[8] = {a0*inv, a1*inv, a2*inv, a3*inv, a4*inv, a5*inv, a6*inv, a7*inv};
    float ss = 0.f;
    #pragma unroll
    for (int k = 0; k < 8; k++) {
        v[k] = (v[k] > 0.0f) ? v[k] : ACT_SLOPE * v[k];
        ss = fmaf(v[k], v[k], ss);
    }
    #pragma unroll
    for (int o = 16; o > 0; o >>= 1) ss += __shfl_xor_sync(0xffffffffu, ss, o);

    // expmap0 + proj over the full 256-wide row
    float nrm = sqrtf(ss);
    float un  = fmaxf(nrm, EPS);
    float th  = tanhf(un);
    float f   = th / un;
    float pn  = fmaxf(f * nrm, EPS);
    if (pn > MAXNORM) f *= MAXNORM / pn;

    float4 o0 = make_float4(v[0]*f, v[1]*f, v[2]*f, v[3]*f);
    float4 o1 = make_float4(v[4]*f, v[5]*f, v[6]*f, v[7]*f);
    float* row = out + (size_t)wid * 256 + lane * 8;
    *reinterpret_cast<float4*>(row)     = o0;
    *reinterpret_cast<float4*>(row + 4) = o1;
}

// ---------------- launch ------------------------------------------------------
extern "C" void kernel_launch(void* const* d_in, const int* in_sizes, int n_in,
                              void* d_out, int out_size) {
    const float* x  = (const float*)d_in[0];
    const int*   ei = (const int*)d_in[1];
    const float* W  = (const float*)d_in[2];
    const float* a  = (const float*)d_in[3];
    float* out = (float*)d_out;

    const int n = in_sizes[0] / DMAX;
    const int E = in_sizes[1] / 2;
    const int* src = ei;
    const int* dst = ei + E;

    k_logmap<<<(n + 7) / 8, 256>>>(x, n);

    dim3 g2((n + 63) / 64, HEADS);
    k_gemm<<<g2, 256>>>(W, a, n);

    k_zero<<<(n + 255) / 256, 256>>>(n);
    k_count<<<(E + 255) / 256, 256>>>(src, E);
    int G = (n + 1023) / 1024;
    k_scan1<<<G, 1024>>>(n);
    k_scan2<<<1, 32>>>(n, G);
    k_scan3<<<G, 1024>>>(n);
    k_scatter<<<(E + 255) / 256, 256>>>(src, dst, E);

    // fused all-head aggregation + expmap0/proj epilogue
    k_agg_all<<<(n + 7) / 8, 256>>>(n, out);
}

// round 3
// speedup vs baseline: 1.6654x; 1.0955x over previous
#include <cuda_runtime.h>
#include <cuda_bf16.h>
#include <cuda_fp16.h>
#include <math.h>

// Problem constants (fixed by the reference setup)
#define NMAX 100000
#define DMAX 64
#define HEADS 4
#define EMAX 3200000
#define EPS 1e-15f
#define ALPHA 0.2f       // leaky slope inside attention
#define ACT_SLOPE 0.01f  // final leaky slope
#define MAXNORM 0.996f   // (1 - 4e-3)/sqrt(c), c=1

// ---------------- device scratch (static; no runtime allocation) -------------
__device__ __half g_hh[(size_t)NMAX * 256];      // 51.2 MB  h interleaved [node][hd*64+c]
__device__ float  g_ssrc4[NMAX * 4];             // scores interleaved [node][hd]
__device__ float  g_sdst4[NMAX * 4];
__device__ int    g_deg[NMAX];
__device__ int    g_rowptr[NMAX + 1];
__device__ int    g_cursor[NMAX];
__device__ int    g_dsts[EMAX];                  // dst sorted by src (CSR payload)
__device__ int    g_bsum[1024];

// ---------------- K1: fused logmap0 + all-head GEMM + score projections ------
// One block = 64-row tile. Loads X once, computes logmap in smem, then loops
// the 4 heads reusing the tangent-space tile. Writes h fp16 interleaved.
__global__ __launch_bounds__(256) void k_gemm_all(const float* __restrict__ x,
                                                  const float* __restrict__ W,
                                                  const float* __restrict__ a,
                                                  int n) {
    const int row0 = blockIdx.x * 64;
    __shared__ float Xs[64 * 64];
    __shared__ float Ws[64 * 64];
    __shared__ float As[128];
    const int tid = threadIdx.x;

    // load X tile (zero-fill OOB rows)
    for (int i = tid; i < 4096; i += 256) {
        int r = row0 + (i >> 6);
        Xs[i] = (r < n) ? x[(size_t)r * DMAX + (i & 63)] : 0.0f;
    }
    __syncthreads();

    // logmap0 in place: 4 threads per row, 16 elements each
    {
        int r = tid >> 2, q = tid & 3;
        float* rp = Xs + r * 64 + q * 16;
        float ss = 0.0f;
        #pragma unroll
        for (int k = 0; k < 16; k++) ss = fmaf(rp[k], rp[k], ss);
        ss += __shfl_xor_sync(0xffffffffu, ss, 1);
        ss += __shfl_xor_sync(0xffffffffu, ss, 2);
        float nrm = fmaxf(sqrtf(ss), EPS);
        float cl  = fminf(nrm, 1.0f - 1e-7f);
        float at  = 0.5f * (log1pf(cl) - log1pf(-cl));   // artanh
        float f   = at / nrm;
        #pragma unroll
        for (int k = 0; k < 16; k++) rp[k] *= f;
    }

    const int ty = tid >> 4;   // 0..15 (row group)
    const int tx = tid & 15;   // 0..15 (col group)

    for (int hd = 0; hd < HEADS; hd++) {
        __syncthreads();   // previous head's compute done before Ws overwrite
        for (int i = tid; i < 4096; i += 256) Ws[i] = W[hd * 4096 + i];
        if (tid < 128) As[tid] = a[hd * 128 + tid];
        __syncthreads();

        float acc[4][4];
        #pragma unroll
        for (int i = 0; i < 4; i++)
            #pragma unroll
            for (int j = 0; j < 4; j++) acc[i][j] = 0.0f;

        #pragma unroll 8
        for (int k = 0; k < 64; k++) {
            float4 wv = *reinterpret_cast<const float4*>(&Ws[k * 64 + tx * 4]);
            #pragma unroll
            for (int i = 0; i < 4; i++) {
                float xv = Xs[(ty * 4 + i) * 64 + k];
                acc[i][0] = fmaf(xv, wv.x, acc[i][0]);
                acc[i][1] = fmaf(xv, wv.y, acc[i][1]);
                acc[i][2] = fmaf(xv, wv.z, acc[i][2]);
                acc[i][3] = fmaf(xv, wv.w, acc[i][3]);
            }
        }

        float al0 = As[tx*4+0], al1 = As[tx*4+1], al2 = As[tx*4+2], al3 = As[tx*4+3];
        float ar0 = As[64+tx*4+0], ar1 = As[64+tx*4+1], ar2 = As[64+tx*4+2], ar3 = As[64+tx*4+3];
        #pragma unroll
        for (int i = 0; i < 4; i++) {
            int r = row0 + ty * 4 + i;
            if (r < n) {
                size_t off = (size_t)r * 256 + hd * 64 + tx * 4;
                __half2 p0 = __floats2half2_rn(acc[i][0], acc[i][1]);
                __half2 p1 = __floats2half2_rn(acc[i][2], acc[i][3]);
                *reinterpret_cast<__half2*>(&g_hh[off])     = p0;
                *reinterpret_cast<__half2*>(&g_hh[off + 2]) = p1;
            }
            float pl = acc[i][0]*al0 + acc[i][1]*al1 + acc[i][2]*al2 + acc[i][3]*al3;
            float pr = acc[i][0]*ar0 + acc[i][1]*ar1 + acc[i][2]*ar2 + acc[i][3]*ar3;
            #pragma unroll
            for (int o = 8; o > 0; o >>= 1) {
                pl += __shfl_xor_sync(0xffffffffu, pl, o);
                pr += __shfl_xor_sync(0xffffffffu, pr, o);
            }
            if (tx == 0 && r < n) { g_ssrc4[r * 4 + hd] = pl; g_sdst4[r * 4 + hd] = pr; }
        }
    }
}

// ---------------- K3: CSR construction ---------------------------------------
__global__ void k_zero(int n) {
    int i = blockIdx.x * blockDim.x + threadIdx.x;
    if (i < n) g_deg[i] = 0;
}
// 4 edges per thread: 4 independent atomics in flight (latency-bound otherwise)
__global__ void k_count4(const int* __restrict__ src, int e) {
    int base = (blockIdx.x * blockDim.x + threadIdx.x) * 4;
    if (base + 3 < e) {
        int4 s = *reinterpret_cast<const int4*>(src + base);
        atomicAdd(&g_deg[s.x], 1);
        atomicAdd(&g_deg[s.y], 1);
        atomicAdd(&g_deg[s.z], 1);
        atomicAdd(&g_deg[s.w], 1);
    } else {
        for (int k = 0; k < 4; k++)
            if (base + k < e) atomicAdd(&g_deg[src[base + k]], 1);
    }
}
__global__ __launch_bounds__(1024) void k_scan1(int n) {
    __shared__ int s[1024];
    int t = threadIdx.x;
    int i = blockIdx.x * 1024 + t;
    int v = (i < n) ? g_deg[i] : 0;
    s[t] = v;
    #pragma unroll
    for (int off = 1; off < 1024; off <<= 1) {
        __syncthreads();
        int add = (t >= off) ? s[t - off] : 0;
        __syncthreads();
        s[t] += add;
    }
    __syncthreads();
    if (i < n) g_rowptr[i] = s[t] - v;      // exclusive within block
    if (t == 1023) g_bsum[blockIdx.x] = s[1023];
}
// parallel scan of per-block sums (nblk <= 1024)
__global__ __launch_bounds__(1024) void k_scan2(int n, int nblk) {
    __shared__ int s[1024];
    int t = threadIdx.x;
    int v = (t < nblk) ? g_bsum[t] : 0;
    s[t] = v;
    #pragma unroll
    for (int off = 1; off < 1024; off <<= 1) {
        __syncthreads();
        int add = (t >= off) ? s[t - off] : 0;
        __syncthreads();
        s[t] += add;
    }
    __syncthreads();
    if (t < nblk) g_bsum[t] = s[t] - v;     // exclusive
    if (t == nblk - 1) g_rowptr[n] = s[t];  // total
}
__global__ __launch_bounds__(1024) void k_scan3(int n) {
    int i = blockIdx.x * 1024 + threadIdx.x;
    if (i < n) {
        int v = g_rowptr[i] + g_bsum[blockIdx.x];
        g_rowptr[i] = v;
        g_cursor[i] = v;
    }
}
__global__ void k_scatter4(const int* __restrict__ src, const int* __restrict__ dst, int e) {
    int base = (blockIdx.x * blockDim.x + threadIdx.x) * 4;
    if (base + 3 < e) {
        int4 s = *reinterpret_cast<const int4*>(src + base);
        int4 d = *reinterpret_cast<const int4*>(dst + base);
        int p0 = atomicAdd(&g_cursor[s.x], 1);
        int p1 = atomicAdd(&g_cursor[s.y], 1);
        int p2 = atomicAdd(&g_cursor[s.z], 1);
        int p3 = atomicAdd(&g_cursor[s.w], 1);
        g_dsts[p0] = d.x; g_dsts[p1] = d.y; g_dsts[p2] = d.z; g_dsts[p3] = d.w;
    } else {
        for (int k = 0; k < 4; k++)
            if (base + k < e) {
                int p = atomicAdd(&g_cursor[src[base + k]], 1);
                g_dsts[p] = dst[base + k];
            }
    }
}

// ---------------- K4: fused aggregation, all heads + expmap0/proj ------------
// Warp per node; lane L owns cols [L*8,L*8+8), head = L>>3.
// Manual 4x unroll: batch the dst-index loads, then 4 independent 16B gathers
// (breaks the dst->h dependence chain; MLP 1 -> 4 on the L2 critical path).
__global__ __launch_bounds__(256) void k_agg_all(int n, float* __restrict__ out) {
    int wid  = (blockIdx.x * blockDim.x + threadIdx.x) >> 5;
    int lane = threadIdx.x & 31;
    if (wid >= n) return;
    const int hd  = lane >> 3;
    const int beg = g_rowptr[wid];
    const int end = g_rowptr[wid + 1];
    const float ssn = g_ssrc4[wid * 4 + hd];

    float a0=0.f,a1=0.f,a2=0.f,a3=0.f,a4=0.f,a5=0.f,a6=0.f,a7=0.f;
    float den = 0.f;

    int e = beg;
    for (; e + 3 < end; e += 4) {
        int d0 = __ldg(&g_dsts[e+0]);
        int d1 = __ldg(&g_dsts[e+1]);
        int d2 = __ldg(&g_dsts[e+2]);
        int d3 = __ldg(&g_dsts[e+3]);
        float t0 = __ldg(&g_sdst4[d0*4+hd]);
        float t1 = __ldg(&g_sdst4[d1*4+hd]);
        float t2 = __ldg(&g_sdst4[d2*4+hd]);
        float t3 = __ldg(&g_sdst4[d3*4+hd]);
        uint4 h0 = *reinterpret_cast<const uint4*>(&g_hh[(size_t)d0*256 + lane*8]);
        uint4 h1 = *reinterpret_cast<const uint4*>(&g_hh[(size_t)d1*256 + lane*8]);
        uint4 h2 = *reinterpret_cast<const uint4*>(&g_hh[(size_t)d2*256 + lane*8]);
        uint4 h3 = *reinterpret_cast<const uint4*>(&g_hh[(size_t)d3*256 + lane*8]);
        float s0 = ssn + t0; s0 = (s0 > 0.f) ? s0 : ALPHA * s0;
        float s1 = ssn + t1; s1 = (s1 > 0.f) ? s1 : ALPHA * s1;
        float s2 = ssn + t2; s2 = (s2 > 0.f) ? s2 : ALPHA * s2;
        float s3 = ssn + t3; s3 = (s3 > 0.f) ? s3 : ALPHA * s3;
        float w0 = __expf(-s0), w1 = __expf(-s1), w2 = __expf(-s2), w3 = __expf(-s3);
        #define ACC(HV, W) { \
            float2 f0 = __half22float2(*reinterpret_cast<__half2*>(&HV.x)); \
            float2 f1 = __half22float2(*reinterpret_cast<__half2*>(&HV.y)); \
            float2 f2 = __half22float2(*reinterpret_cast<__half2*>(&HV.z)); \
            float2 f3 = __half22float2(*reinterpret_cast<__half2*>(&HV.w)); \
            a0 = fmaf(W, f0.x, a0); a1 = fmaf(W, f0.y, a1); \
            a2 = fmaf(W, f1.x, a2); a3 = fmaf(W, f1.y, a3); \
            a4 = fmaf(W, f2.x, a4); a5 = fmaf(W, f2.y, a5); \
            a6 = fmaf(W, f3.x, a6); a7 = fmaf(W, f3.y, a7); }
        ACC(h0, w0); ACC(h1, w1); ACC(h2, w2); ACC(h3, w3);
        den += (w0 + w1) + (w2 + w3);
    }
    for (; e < end; e++) {
        int d = __ldg(&g_dsts[e]);
        float s = ssn + __ldg(&g_sdst4[d*4+hd]);
        s = (s > 0.f) ? s : ALPHA * s;
        float w = __expf(-s);
        uint4 hv = *reinterpret_cast<const uint4*>(&g_hh[(size_t)d*256 + lane*8]);
        ACC(hv, w);
        den += w;
    }
    #undef ACC

    float inv = 1.0f / (den + EPS);
    float v[8] = {a0*inv, a1*inv, a2*inv, a3*inv, a4*inv, a5*inv, a6*inv, a7*inv};
    float ss = 0.f;
    #pragma unroll
    for (int k = 0; k < 8; k++) {
        v[k] = (v[k] > 0.0f) ? v[k] : ACT_SLOPE * v[k];
        ss = fmaf(v[k], v[k], ss);
    }
    #pragma unroll
    for (int o = 16; o > 0; o >>= 1) ss += __shfl_xor_sync(0xffffffffu, ss, o);

    float nrm = sqrtf(ss);
    float un  = fmaxf(nrm, EPS);
    float th  = tanhf(un);
    float f   = th / un;
    float pn  = fmaxf(f * nrm, EPS);
    if (pn > MAXNORM) f *= MAXNORM / pn;

    float* row = out + (size_t)wid * 256 + lane * 8;
    *reinterpret_cast<float4*>(row)     = make_float4(v[0]*f, v[1]*f, v[2]*f, v[3]*f);
    *reinterpret_cast<float4*>(row + 4) = make_float4(v[4]*f, v[5]*f, v[6]*f, v[7]*f);
}

// ---------------- launch ------------------------------------------------------
extern "C" void kernel_launch(void* const* d_in, const int* in_sizes, int n_in,
                              void* d_out, int out_size) {
    const float* x  = (const float*)d_in[0];
    const int*   ei = (const int*)d_in[1];
    const float* W  = (const float*)d_in[2];
    const float* a  = (const float*)d_in[3];
    float* out = (float*)d_out;

    const int n = in_sizes[0] / DMAX;
    const int E = in_sizes[1] / 2;
    const int* src = ei;
    const int* dst = ei + E;

    k_gemm_all<<<(n + 63) / 64, 256>>>(x, W, a, n);

    k_zero<<<(n + 255) / 256, 256>>>(n);
    int eq = (E + 3) / 4;
    k_count4<<<(eq + 255) / 256, 256>>>(src, E);
    int G = (n + 1023) / 1024;
    k_scan1<<<G, 1024>>>(n);
    k_scan2<<<1, 1024>>>(n, G);
    k_scan3<<<G, 1024>>>(n);
    k_scatter4<<<(eq + 255) / 256, 256>>>(src, dst, E);

    // fused all-head aggregation + expmap0/proj epilogue
    k_agg_all<<<(n + 7) / 8, 256>>>(n, out);
}